// round 10
// baseline (speedup 1.0000x reference)
#include <cuda_runtime.h>

#define NQ  14
#define BLK 32     // single-warp CTAs; params broadcast via shuffles (no SMEM/BAR)

// Analytic evaluation of the QuantumGate circuit via a 4-real-variable
// transfer recursion (derivation R3-R6).
//
// Per qubit q (shared: cp=cos p0, sp=sin p0, C=cos p1, S=sin p1;
// per-thread: cx=cos x_q, sx=sin x_q):
//   D = cp*cx,  g = sp*cx,  state (S1,S2,u2r,u2i) init (1,1,0,0):
//   S1' = C*(D*S2 + sx*u2i)        u2r' = -S*(g*S1 + u2r)
//   S2' = C*(S1 + g*u2r)           u2i' = -S*(D*u2i - sx*S2)
//   <Z_q> = S1' + rho*u2r',  rho = sp[q+1]*cx[q+1]  (rho_13 = 1)

__global__ void __launch_bounds__(BLK)
quantum_gate_kernel(const float* __restrict__ x,
                    const float* __restrict__ params,
                    float* __restrict__ out, int B)
{
    const int lane = threadIdx.x;
    int b = blockIdx.x * BLK + lane;
    if (b >= B) b = B - 1;      // clamp: duplicate threads write identical values

    // ---- Issue x loads FIRST (7x LDG.64, MLP=7; overlaps the params leg) ----
    float xv[NQ];
    {
        const float2* gx = (const float2*)(x + (size_t)b * NQ);
#pragma unroll
        for (int i = 0; i < NQ / 2; i++) {
            float2 v = gx[i];
            xv[2 * i] = v.x;
            xv[2 * i + 1] = v.y;
        }
    }

    // ---- Param trig: one sincos per lane (< 28), broadcast via shuffles ----
    float my_sin = 0.0f, my_cos = 0.0f;
    if (lane < 2 * NQ) {
        float p = __ldg(&params[lane]);
        __sincosf(p, &my_sin, &my_cos);
    }

    // ---- Per-thread x trig (independent MUFU chains) ----
    float cx_[NQ], sx_[NQ];
#pragma unroll
    for (int q = 0; q < NQ; q++)
        __sincosf(xv[q], &sx_[q], &cx_[q]);

    // ---- Broadcast param trig into registers (compile-time lane indices;
    //      off the serial chain, hoisted by ptxas) ----
    float cp0[NQ], sp0[NQ], C_[NQ], Sn_[NQ];
#pragma unroll
    for (int q = 0; q < NQ; q++) {
        cp0[q] =  __shfl_sync(0xFFFFFFFF, my_cos, q);
        sp0[q] =  __shfl_sync(0xFFFFFFFF, my_sin, q);
        C_[q]  =  __shfl_sync(0xFFFFFFFF, my_cos, NQ + q);
        Sn_[q] = -__shfl_sync(0xFFFFFFFF, my_sin, NQ + q);
    }

    // ---- 4-variable serial recursion; store pairs as they complete ----
    float S1 = 1.0f, S2 = 1.0f, u2r = 0.0f, u2i = 0.0f;
    float2* go = (float2*)(out + (size_t)b * NQ);
    float o_prev = 0.0f;

#pragma unroll
    for (int q = 0; q < NQ; q++) {
        const float cx = cx_[q], sx = sx_[q];
        const float D = cp0[q] * cx;        // cos(p0)*cos(x)
        const float g = sp0[q] * cx;        // sin(p0)*cos(x)
        const float C = C_[q], Sn = Sn_[q];

        float nS1  = C  * fmaf(D, S2, sx * u2i);
        float nS2  = C  * fmaf(g, u2r, S1);
        float nu2r = Sn * fmaf(g, S1, u2r);
        float nu2i = Sn * fmaf(D, u2i, -sx * S2);

        S1 = nS1; S2 = nS2; u2r = nu2r; u2i = nu2i;

        float rho = (q < NQ - 1) ? sp0[q + 1] * cx_[q + 1] : 1.0f;
        float oq = fmaf(rho, u2r, S1);

        if (q & 1) {
            float2 v; v.x = o_prev; v.y = oq;
            go[q >> 1] = v;                  // STG.64 issued as soon as ready
        } else {
            o_prev = oq;
        }
    }
}

extern "C" void kernel_launch(void* const* d_in, const int* in_sizes, int n_in,
                              void* d_out, int out_size) {
    const float* x      = (const float*)d_in[0];   // (B, 14) float32
    const float* params = (const float*)d_in[1];   // (28,)   float32
    float* out = (float*)d_out;                    // (B, 14) float32

    int B = in_sizes[0] / NQ;
    int blocks = (B + BLK - 1) / BLK;              // B=4096 -> 128 CTAs
    quantum_gate_kernel<<<blocks, BLK>>>(x, params, out, B);
}

// round 11
// speedup vs baseline: 1.4178x; 1.4178x over previous
#include <cuda_runtime.h>

#define NQ  14
#define BLK 32     // single-warp CTAs; params broadcast via shuffles (no SMEM/BAR)

// Analytic evaluation of the QuantumGate circuit via a 4-real-variable
// transfer recursion (derivation R3-R6).
//
// Per qubit q (shared: cp=cos p0, sp=sin p0, C=cos p1, S=sin p1;
// per-thread: cx=cos x_q, sx=sin x_q):
//   D = cp*cx,  g = sp*cx,  state (S1,S2,u2r,u2i) init (1,1,0,0):
//   S1' = C*(D*S2 + sx*u2i)        u2r' = -S*(g*S1 + u2r)
//   S2' = C*(S1 + g*u2r)           u2i' = -S*(D*u2i - sx*S2)
//   <Z_q> = S1' + rho*u2r',  rho = g[q+1]  (rho_13 = 1)

__global__ void __launch_bounds__(BLK)
quantum_gate_kernel(const float* __restrict__ x,
                    const float* __restrict__ params,
                    float* __restrict__ out, int B)
{
    const int lane = threadIdx.x;
    int b = blockIdx.x * BLK + lane;
    if (b >= B) b = B - 1;      // clamp: duplicate threads write identical values

    // ---- Issue x loads FIRST (7x LDG.64, MLP=7; overlaps the params leg) ----
    float xv[NQ];
    {
        const float2* gx = (const float2*)(x + (size_t)b * NQ);
#pragma unroll
        for (int i = 0; i < NQ / 2; i++) {
            float2 v = gx[i];
            xv[2 * i] = v.x;
            xv[2 * i + 1] = v.y;
        }
    }

    // ---- Param trig: one sincos per lane (< 28), broadcast via shuffles ----
    float my_sin = 0.0f, my_cos = 0.0f;
    if (lane < 2 * NQ) {
        float p = __ldg(&params[lane]);
        __sincosf(p, &my_sin, &my_cos);
    }

    // ---- Per-thread x trig (independent MUFU chains) ----
    float cx_[NQ], sx_[NQ];
#pragma unroll
    for (int q = 0; q < NQ; q++)
        __sincosf(xv[q], &sx_[q], &cx_[q]);

    // ---- Broadcast param trig (compile-time lane idx; off the serial chain),
    //      then fold into per-qubit D/g so the recursion body is 3 ops deep ----
    float D_[NQ], g_[NQ], C_[NQ], Sn_[NQ];
#pragma unroll
    for (int q = 0; q < NQ; q++) {
        float cp0 = __shfl_sync(0xFFFFFFFF, my_cos, q);
        float sp0 = __shfl_sync(0xFFFFFFFF, my_sin, q);
        C_[q]  =  __shfl_sync(0xFFFFFFFF, my_cos, NQ + q);
        Sn_[q] = -__shfl_sync(0xFFFFFFFF, my_sin, NQ + q);
        D_[q] = cp0 * cx_[q];      // cos(p0)*cos(x)
        g_[q] = sp0 * cx_[q];      // sin(p0)*cos(x)  (also rho_{q-1})
    }

    // ---- 4-variable serial recursion; store pairs as they complete ----
    float S1 = 1.0f, S2 = 1.0f, u2r = 0.0f, u2i = 0.0f;
    float2* go = (float2*)(out + (size_t)b * NQ);
    float o_prev = 0.0f;

#pragma unroll
    for (int q = 0; q < NQ; q++) {
        const float cx = cx_[q], sx = sx_[q];
        const float D = D_[q], g = g_[q];
        const float C = C_[q], Sn = Sn_[q];

        float nS1  = C  * fmaf(D, S2, sx * u2i);
        float nS2  = C  * fmaf(g, u2r, S1);
        float nu2r = Sn * fmaf(g, S1, u2r);
        float nu2i = Sn * fmaf(D, u2i, -sx * S2);

        S1 = nS1; S2 = nS2; u2r = nu2r; u2i = nu2i;

        float rho = (q < NQ - 1) ? g_[q + 1] : 1.0f;
        float oq = fmaf(rho, u2r, S1);

        if (q & 1) {
            float2 v; v.x = o_prev; v.y = oq;
            go[q >> 1] = v;                  // STG.64 issued as soon as ready
        } else {
            o_prev = oq;
        }
    }
}

extern "C" void kernel_launch(void* const* d_in, const int* in_sizes, int n_in,
                              void* d_out, int out_size) {
    const float* x      = (const float*)d_in[0];   // (B, 14) float32
    const float* params = (const float*)d_in[1];   // (28,)   float32
    float* out = (float*)d_out;                    // (B, 14) float32

    int B = in_sizes[0] / NQ;
    int blocks = (B + BLK - 1) / BLK;              // B=4096 -> 128 CTAs
    quantum_gate_kernel<<<blocks, BLK>>>(x, params, out, B);
}